// round 1
// baseline (speedup 1.0000x reference)
#include <cuda_runtime.h>
#include <cuda_bf16.h>
#include <cstdint>

// ---------------------------------------------------------------------------
// Problem constants
// ---------------------------------------------------------------------------
#define B_WIN   2048          // windows*batch
#define NTOK    49            // tokens per window
#define DMODEL  768
#define NHEADS  24
#define HDIM    32
#define NW      64            // windows per image (mask dim 0)
#define MROWS   (B_WIN * NTOK)   // 100352
#define QKV_N   (3 * DMODEL)     // 2304

// scratch (allocation-free: __device__ globals)
__device__ float g_qkv[(size_t)MROWS * QKV_N];   // (B*49, 2304)
__device__ float g_att[(size_t)MROWS * DMODEL];  // (B*49, 768)

// ---------------------------------------------------------------------------
// packed fp32x2 helpers (Blackwell FFMA2 path — only reachable via PTX)
// ---------------------------------------------------------------------------
__device__ __forceinline__ unsigned long long dup_f32(float x) {
    unsigned long long r;
    asm("mov.b64 %0, {%1, %1};" : "=l"(r) : "f"(x));
    return r;
}
__device__ __forceinline__ void fma2(unsigned long long& d,
                                     unsigned long long a,
                                     unsigned long long b) {
    asm("fma.rn.f32x2 %0, %1, %2, %0;" : "+l"(d) : "l"(a), "l"(b));
}
__device__ __forceinline__ void unpack2(unsigned long long v, float& lo, float& hi) {
    asm("mov.b64 {%0, %1}, %2;" : "=f"(lo), "=f"(hi) : "l"(v));
}

// ---------------------------------------------------------------------------
// SGEMM: C[M,N] = A[M,K] @ B[K,N] + bias[N]
// A row-major, B row-major. M % 128 == 0, N % 128 == 0, K % 16 == 0.
// BM=BN=128, BK=16, 256 threads, 8x8 per thread, packed f32x2 accumulation.
// ---------------------------------------------------------------------------
#define BM 128
#define BN 128
#define BK 16
#define ASTRIDE (BM + 4)   // pad: keeps 16B alignment, reduces STS conflicts

__global__ void __launch_bounds__(256)
sgemm_bias_kernel(const float* __restrict__ A,
                  const float* __restrict__ B,
                  const float* __restrict__ bias,
                  float* __restrict__ C,
                  int M, int N, int K)
{
    __shared__ float As[BK][ASTRIDE];
    __shared__ float Bs[BK][BN];

    const int tid = threadIdx.x;
    const int tx  = tid & 15;        // 0..15 (col groups of 8)
    const int ty  = tid >> 4;        // 0..15 (row groups of 8)

    const int block_row = blockIdx.y * BM;
    const int block_col = blockIdx.x * BN;

    // accumulators: acc[c][rp] packs rows (2rp, 2rp+1) for column c
    unsigned long long acc[8][4];
#pragma unroll
    for (int c = 0; c < 8; c++)
#pragma unroll
        for (int rp = 0; rp < 4; rp++) acc[c][rp] = 0ull;

    for (int k0 = 0; k0 < K; k0 += BK) {
        // ---- load A tile (128x16), store transposed into As[k][m] ----
#pragma unroll
        for (int l = 0; l < 2; l++) {
            int f   = tid + l * 256;      // 0..511
            int row = f >> 2;             // 0..127
            int kc  = (f & 3) << 2;       // 0,4,8,12
            float4 av = *reinterpret_cast<const float4*>(
                A + (size_t)(block_row + row) * K + k0 + kc);
            As[kc + 0][row] = av.x;
            As[kc + 1][row] = av.y;
            As[kc + 2][row] = av.z;
            As[kc + 3][row] = av.w;
        }
        // ---- load B tile (16x128) ----
#pragma unroll
        for (int l = 0; l < 2; l++) {
            int f    = tid + l * 256;     // 0..511
            int brow = f >> 5;            // 0..15
            int bcol = (f & 31) << 2;     // 0..124
            *reinterpret_cast<float4*>(&Bs[brow][bcol]) =
                *reinterpret_cast<const float4*>(
                    B + (size_t)(k0 + brow) * N + block_col + bcol);
        }
        __syncthreads();

#pragma unroll
        for (int k = 0; k < BK; k++) {
            // a: 8 floats = 4 packed row-pairs (free packing via 16B loads)
            ulonglong2 aA = *reinterpret_cast<const ulonglong2*>(&As[k][ty * 8]);
            ulonglong2 aB = *reinterpret_cast<const ulonglong2*>(&As[k][ty * 8 + 4]);
            unsigned long long ar[4] = { aA.x, aA.y, aB.x, aB.y };
            // b: 8 floats, duplicated per column
            float4 b0 = *reinterpret_cast<const float4*>(&Bs[k][tx * 8]);
            float4 b1 = *reinterpret_cast<const float4*>(&Bs[k][tx * 8 + 4]);
            unsigned long long bd[8];
            bd[0] = dup_f32(b0.x); bd[1] = dup_f32(b0.y);
            bd[2] = dup_f32(b0.z); bd[3] = dup_f32(b0.w);
            bd[4] = dup_f32(b1.x); bd[5] = dup_f32(b1.y);
            bd[6] = dup_f32(b1.z); bd[7] = dup_f32(b1.w);
#pragma unroll
            for (int c = 0; c < 8; c++)
#pragma unroll
                for (int rp = 0; rp < 4; rp++)
                    fma2(acc[c][rp], ar[rp], bd[c]);
        }
        __syncthreads();
    }

    // ---- epilogue: unpack, add bias, vectorized stores ----
    float bias_v[8];
#pragma unroll
    for (int c = 0; c < 8; c++) bias_v[c] = bias[block_col + tx * 8 + c];

    const size_t row0 = (size_t)block_row + ty * 8;
#pragma unroll
    for (int rp = 0; rp < 4; rp++) {
        float lo[8], hi[8];
#pragma unroll
        for (int c = 0; c < 8; c++) {
            float l, h;
            unpack2(acc[c][rp], l, h);
            lo[c] = l + bias_v[c];
            hi[c] = h + bias_v[c];
        }
        float* p0 = C + (row0 + 2 * rp)     * N + block_col + tx * 8;
        float* p1 = C + (row0 + 2 * rp + 1) * N + block_col + tx * 8;
        *reinterpret_cast<float4*>(p0)     = make_float4(lo[0], lo[1], lo[2], lo[3]);
        *reinterpret_cast<float4*>(p0 + 4) = make_float4(lo[4], lo[5], lo[6], lo[7]);
        *reinterpret_cast<float4*>(p1)     = make_float4(hi[0], hi[1], hi[2], hi[3]);
        *reinterpret_cast<float4*>(p1 + 4) = make_float4(hi[4], hi[5], hi[6], hi[7]);
    }
}

// ---------------------------------------------------------------------------
// Attention kernel: one CTA per (window b, head h).
// q,k,v: 49x32 fp32 slices of g_qkv. k stored transposed in smem for
// conflict-free lane-wise dot products. Warp-per-row softmax.
// ---------------------------------------------------------------------------
#define KT_STRIDE 50  // pad 49 -> 50

__global__ void __launch_bounds__(128)
attn_kernel(const float* __restrict__ qkv,
            const float* __restrict__ mask,        // (64,49,49)
            const float* __restrict__ bias_table,  // (169,24)
            float* __restrict__ out)               // (B*49, 768)
{
    const int bh = blockIdx.x;
    const int b  = bh / NHEADS;
    const int h  = bh - b * NHEADS;
    const int w  = b & (NW - 1);     // b % 64

    __shared__ float qs[NTOK * HDIM];        // q[i][d]
    __shared__ float kt[HDIM * KT_STRIDE];   // k^T[d][j]
    __shared__ float vs[NTOK * HDIM];        // v[j][d]
    __shared__ float pbuf[4][64];

    const int tid = threadIdx.x;
    const float* base = qkv + (size_t)b * NTOK * QKV_N + h * HDIM;

    for (int idx = tid; idx < NTOK * HDIM; idx += 128) {
        int i = idx >> 5;        // token
        int d = idx & 31;        // dim
        size_t roff = (size_t)i * QKV_N + d;
        qs[idx]               = base[roff];
        kt[d * KT_STRIDE + i] = base[roff + DMODEL];
        vs[idx]               = base[roff + 2 * DMODEL];
    }
    __syncthreads();

    const int warp = tid >> 5;
    const int lane = tid & 31;
    const float scale = 0.17677669529663687f;  // 32^-0.5

    const float* mrow_base = mask + (size_t)w * NTOK * NTOK;

    for (int i = warp; i < NTOK; i += 4) {
        const int yi = i / 7, xi = i - yi * 7;
        const float* mrow = mrow_base + i * NTOK;

        // lane covers j = lane and j = lane + 32 (if < 49)
        float l1, l2 = -1e30f;
        {
            int j = lane;
            float acc = 0.f;
#pragma unroll
            for (int d = 0; d < HDIM; d++)
                acc += qs[i * HDIM + d] * kt[d * KT_STRIDE + j];
            int yj = j / 7, xj = j - yj * 7;
            int ridx = (yi - yj + 6) * 13 + (xi - xj + 6);
            l1 = acc * scale + bias_table[ridx * NHEADS + h] + mrow[j];
        }
        if (lane < NTOK - 32) {
            int j = lane + 32;
            float acc = 0.f;
#pragma unroll
            for (int d = 0; d < HDIM; d++)
                acc += qs[i * HDIM + d] * kt[d * KT_STRIDE + j];
            int yj = j / 7, xj = j - yj * 7;
            int ridx = (yi - yj + 6) * 13 + (xi - xj + 6);
            l2 = acc * scale + bias_table[ridx * NHEADS + h] + mrow[j];
        }

        // warp softmax over 49 logits (each lane holds up to 2)
        float m = fmaxf(l1, l2);
#pragma unroll
        for (int o = 16; o > 0; o >>= 1)
            m = fmaxf(m, __shfl_xor_sync(0xffffffffu, m, o));
        float p1 = __expf(l1 - m);
        float p2 = (lane < NTOK - 32) ? __expf(l2 - m) : 0.f;
        float s = p1 + p2;
#pragma unroll
        for (int o = 16; o > 0; o >>= 1)
            s += __shfl_xor_sync(0xffffffffu, s, o);
        float inv = 1.f / s;

        pbuf[warp][lane] = p1 * inv;
        if (lane < NTOK - 32) pbuf[warp][lane + 32] = p2 * inv;
        __syncwarp();

        // out[i][d] = sum_j p[j] * v[j][d]; lane = d (32 dims exactly)
        float acc = 0.f;
#pragma unroll
        for (int j = 0; j < NTOK; j++)
            acc += pbuf[warp][j] * vs[j * HDIM + lane];
        out[((size_t)b * NTOK + i) * DMODEL + h * HDIM + lane] = acc;
        __syncwarp();
    }
}

// ---------------------------------------------------------------------------
// launch
// ---------------------------------------------------------------------------
extern "C" void kernel_launch(void* const* d_in, const int* in_sizes, int n_in,
                              void* d_out, int out_size)
{
    const float* x          = (const float*)d_in[0];
    const float* mask       = (const float*)d_in[1];
    const float* qkv_w      = (const float*)d_in[2];
    const float* qkv_b      = (const float*)d_in[3];
    const float* proj_w     = (const float*)d_in[4];
    const float* proj_b     = (const float*)d_in[5];
    const float* bias_table = (const float*)d_in[6];
    float* out = (float*)d_out;

    float *qkv_s = nullptr, *att_s = nullptr;
    cudaGetSymbolAddress((void**)&qkv_s, g_qkv);
    cudaGetSymbolAddress((void**)&att_s, g_att);

    // 1) QKV projection: (100352,768) @ (768,2304) + bias
    {
        dim3 grid(QKV_N / BN, MROWS / BM);
        sgemm_bias_kernel<<<grid, 256>>>(x, qkv_w, qkv_b, qkv_s,
                                         MROWS, QKV_N, DMODEL);
    }
    // 2) windowed attention per (window, head)
    attn_kernel<<<B_WIN * NHEADS, 128>>>(qkv_s, mask, bias_table, att_s);

    // 3) output projection: (100352,768) @ (768,768) + bias -> d_out
    {
        dim3 grid(DMODEL / BN, MROWS / BM);
        sgemm_bias_kernel<<<grid, 256>>>(att_s, proj_w, proj_b, out,
                                         MROWS, DMODEL, DMODEL);
    }
}

// round 3
// speedup vs baseline: 1.9761x; 1.9761x over previous
#include <cuda_runtime.h>
#include <cuda_bf16.h>
#include <cstdint>

// ---------------------------------------------------------------------------
// Problem constants
// ---------------------------------------------------------------------------
#define B_WIN   2048
#define NTOK    49
#define DMODEL  768
#define NHEADS  24
#define HDIM    32
#define NW      64
#define MROWS   (B_WIN * NTOK)     // 100352
#define QKV_N   (3 * DMODEL)       // 2304
#define KDIM    768
#define KPITCH  (KDIM * 2)         // bytes per K-major row (bf16)

// ---------------------------------------------------------------------------
// scratch (__device__ globals, allocation-free)
// ---------------------------------------------------------------------------
__device__ float         g_qkv [(size_t)MROWS * QKV_N];
__device__ __nv_bfloat16 g_xhi [(size_t)MROWS * KDIM];
__device__ __nv_bfloat16 g_xlo [(size_t)MROWS * KDIM];
__device__ __nv_bfloat16 g_ahi [(size_t)MROWS * KDIM];
__device__ __nv_bfloat16 g_alo [(size_t)MROWS * KDIM];
__device__ __nv_bfloat16 g_w1hi[(size_t)QKV_N * KDIM];
__device__ __nv_bfloat16 g_w1lo[(size_t)QKV_N * KDIM];
__device__ __nv_bfloat16 g_w2hi[(size_t)DMODEL * KDIM];
__device__ __nv_bfloat16 g_w2lo[(size_t)DMODEL * KDIM];

// ---------------------------------------------------------------------------
// PTX helpers (all legal on base sm_80+ targets)
// ---------------------------------------------------------------------------
__device__ __forceinline__ void cp16(uint32_t dst, const void* src) {
    asm volatile("cp.async.cg.shared.global [%0], [%1], 16;"
                 :: "r"(dst), "l"((unsigned long long)__cvta_generic_to_global(src))
                 : "memory");
}
__device__ __forceinline__ void ldsm4(uint32_t* r, uint32_t addr) {
    asm volatile("ldmatrix.sync.aligned.m8n8.x4.shared.b16 {%0,%1,%2,%3}, [%4];"
                 : "=r"(r[0]), "=r"(r[1]), "=r"(r[2]), "=r"(r[3]) : "r"(addr));
}
__device__ __forceinline__ void mma_bf16(float* c, const uint32_t* a,
                                         uint32_t b0, uint32_t b1) {
    asm volatile(
        "mma.sync.aligned.m16n8k16.row.col.f32.bf16.bf16.f32 "
        "{%0,%1,%2,%3}, {%4,%5,%6,%7}, {%8,%9}, {%0,%1,%2,%3};"
        : "+f"(c[0]), "+f"(c[1]), "+f"(c[2]), "+f"(c[3])
        : "r"(a[0]), "r"(a[1]), "r"(a[2]), "r"(a[3]), "r"(b0), "r"(b1));
}

// ---------------------------------------------------------------------------
// GEMM: C[M,N] = (Ahi+Alo)[M,K] @ (Bhi+Blo)^T[N,K] + bias, fp32 out.
// 3-term split-bf16: AhiBhi + AhiBlo + AloBhi (all into same accumulators).
// BM=128, BN=256, BK=32, 3-stage cp.async pipeline, 256 threads.
// Warp grid 2(m) x 4(n): each warp 64x64 -> 4 m16-tiles x 8 n8-tiles.
// SMEM rows padded to 80B: conflict-free ldmatrix & aligned cp.async.
// ---------------------------------------------------------------------------
#define BM 128
#define BN 256
#define BK 32
#define NCHUNK (KDIM / BK)      // 24
#define ROWB 80
#define AHI_OFF 0
#define ALO_OFF (128 * ROWB)          // 10240
#define BHI_OFF (2 * 128 * ROWB)      // 20480
#define BLO_OFF (BHI_OFF + 256 * ROWB) // 40960
#define STG_B   (BLO_OFF + 256 * ROWB) // 61440
#define SMEM_TOTAL (3 * STG_B)         // 184320

extern __shared__ char dyn_smem[];

__global__ void __launch_bounds__(256, 1)
gemm_mma_kernel(const __nv_bfloat16* __restrict__ Ahi,
                const __nv_bfloat16* __restrict__ Alo,
                const __nv_bfloat16* __restrict__ Bhi,
                const __nv_bfloat16* __restrict__ Blo,
                const float* __restrict__ bias,
                float* __restrict__ C, int N)
{
    const uint32_t sb = (uint32_t)__cvta_generic_to_shared(dyn_smem);
    const int tid    = threadIdx.x;
    const int wid    = tid >> 5;
    const int lane   = tid & 31;
    const int warp_m = wid & 1;     // 0..1  (64 rows each)
    const int warp_n = wid >> 1;    // 0..3  (64 cols each)
    const int brow   = blockIdx.y * BM;
    const int bcol   = blockIdx.x * BN;

    const char* pAhi = (const char*)Ahi + (size_t)brow * KPITCH;
    const char* pAlo = (const char*)Alo + (size_t)brow * KPITCH;
    const char* pBhi = (const char*)Bhi + (size_t)bcol * KPITCH;
    const char* pBlo = (const char*)Blo + (size_t)bcol * KPITCH;

    float acc[4][8][4];
#pragma unroll
    for (int mt = 0; mt < 4; mt++)
#pragma unroll
        for (int nt = 0; nt < 8; nt++)
#pragma unroll
            for (int q = 0; q < 4; q++) acc[mt][nt][q] = 0.f;

    // ---- stage loader ----
    auto load_stage = [&](int c, int s) {
        const uint32_t st = sb + s * STG_B;
        const int koff = c * (BK * 2);   // 64 bytes
#pragma unroll
        for (int r = 0; r < 2; r++) {            // A hi/lo: 128 rows x 64B
            int p    = tid + r * 256;            // 0..511
            int row  = p >> 2;
            int colb = (p & 3) << 4;
            size_t   go = (size_t)row * KPITCH + koff + colb;
            uint32_t so = row * ROWB + colb;
            cp16(st + AHI_OFF + so, pAhi + go);
            cp16(st + ALO_OFF + so, pAlo + go);
        }
#pragma unroll
        for (int r = 0; r < 4; r++) {            // B hi/lo: 256 rows x 64B
            int p    = tid + r * 256;            // 0..1023
            int row  = p >> 2;
            int colb = (p & 3) << 4;
            size_t   go = (size_t)row * KPITCH + koff + colb;
            uint32_t so = row * ROWB + colb;
            cp16(st + BHI_OFF + so, pBhi + go);
            cp16(st + BLO_OFF + so, pBlo + go);
        }
        asm volatile("cp.async.commit_group;" ::: "memory");
    };

    load_stage(0, 0);
    load_stage(1, 1);

    for (int c = 0; c < NCHUNK; c++) {
        if (c < NCHUNK - 1)
            asm volatile("cp.async.wait_group 1;" ::: "memory");
        else
            asm volatile("cp.async.wait_group 0;" ::: "memory");
        __syncthreads();

        if (c + 2 < NCHUNK) load_stage(c + 2, (c + 2) % 3);

        // ---- compute stage c%3 ----
        const uint32_t st = sb + (c % 3) * STG_B;
#pragma unroll
        for (int ks = 0; ks < 2; ks++) {
            const int kb = ks * 32;  // 16 bf16 = 32B per k-step
            uint32_t ahi[4][4], alo[4][4];
#pragma unroll
            for (int mt = 0; mt < 4; mt++) {
                int row = warp_m * 64 + mt * 16 + (lane & 7) + ((lane >> 3) & 1) * 8;
                uint32_t addr = st + row * ROWB + kb + ((lane >> 4) & 1) * 16;
                ldsm4(ahi[mt], addr + AHI_OFF);
                ldsm4(alo[mt], addr + ALO_OFF);
            }
#pragma unroll
            for (int np = 0; np < 4; np++) {
                int rowb = warp_n * 64 + np * 16 + (lane & 7) + ((lane >> 4) & 1) * 8;
                uint32_t addr = st + rowb * ROWB + kb + ((lane >> 3) & 1) * 16;
                uint32_t bh[4], bl[4];
                ldsm4(bh, addr + BHI_OFF);
                ldsm4(bl, addr + BLO_OFF);
#pragma unroll
                for (int t = 0; t < 2; t++) {
                    const int nt = np * 2 + t, o = t * 2;
#pragma unroll
                    for (int mt = 0; mt < 4; mt++) {
                        mma_bf16(acc[mt][nt], ahi[mt], bh[o], bh[o + 1]);
                        mma_bf16(acc[mt][nt], ahi[mt], bl[o], bl[o + 1]);
                        mma_bf16(acc[mt][nt], alo[mt], bh[o], bh[o + 1]);
                    }
                }
            }
        }
    }

    // ---- epilogue: bias + store ----
    const int row0 = brow + warp_m * 64;
    const int col0 = bcol + warp_n * 64;
#pragma unroll
    for (int mt = 0; mt < 4; mt++) {
#pragma unroll
        for (int nt = 0; nt < 8; nt++) {
            int r  = row0 + mt * 16 + (lane >> 2);
            int cc = col0 + nt * 8 + (lane & 3) * 2;
            float2 bv = *(const float2*)(bias + cc);
            float2 o0 = make_float2(acc[mt][nt][0] + bv.x, acc[mt][nt][1] + bv.y);
            float2 o1 = make_float2(acc[mt][nt][2] + bv.x, acc[mt][nt][3] + bv.y);
            *(float2*)(C + (size_t)r * N + cc)       = o0;
            *(float2*)(C + (size_t)(r + 8) * N + cc) = o1;
        }
    }
}

// ---------------------------------------------------------------------------
// split f32 -> (hi, lo) bf16
// ---------------------------------------------------------------------------
__global__ void __launch_bounds__(256)
split_kernel(const float4* __restrict__ in, uint2* __restrict__ hi,
             uint2* __restrict__ lo, int n4)
{
    int i = blockIdx.x * 256 + threadIdx.x;
    if (i >= n4) return;
    float4 v = in[i];
    __nv_bfloat16 h0 = __float2bfloat16(v.x);
    __nv_bfloat16 h1 = __float2bfloat16(v.y);
    __nv_bfloat16 h2 = __float2bfloat16(v.z);
    __nv_bfloat16 h3 = __float2bfloat16(v.w);
    __nv_bfloat16 l0 = __float2bfloat16(v.x - __bfloat162float(h0));
    __nv_bfloat16 l1 = __float2bfloat16(v.y - __bfloat162float(h1));
    __nv_bfloat16 l2 = __float2bfloat16(v.z - __bfloat162float(h2));
    __nv_bfloat16 l3 = __float2bfloat16(v.w - __bfloat162float(h3));
    __nv_bfloat162 hh0 = {h0, h1}, hh1 = {h2, h3};
    __nv_bfloat162 ll0 = {l0, l1}, ll1 = {l2, l3};
    uint2 ho, lw;
    ho.x = *(uint32_t*)&hh0; ho.y = *(uint32_t*)&hh1;
    lw.x = *(uint32_t*)&ll0; lw.y = *(uint32_t*)&ll1;
    hi[i] = ho; lo[i] = lw;
}

// ---------------------------------------------------------------------------
// weight transpose + split: W[K,N] f32 -> hi/lo[N,K] bf16
// ---------------------------------------------------------------------------
__global__ void __launch_bounds__(256)
wtrans_split_kernel(const float* __restrict__ W, __nv_bfloat16* __restrict__ hi,
                    __nv_bfloat16* __restrict__ lo, int K, int N)
{
    __shared__ float t[32][33];
    const int n0 = blockIdx.x * 32, k0 = blockIdx.y * 32;
    const int tx = threadIdx.x & 31, ty = threadIdx.x >> 5;
#pragma unroll
    for (int r = 0; r < 32; r += 8)
        t[ty + r][tx] = W[(size_t)(k0 + ty + r) * N + n0 + tx];
    __syncthreads();
#pragma unroll
    for (int r = 0; r < 32; r += 8) {
        float v = t[tx][ty + r];
        size_t o = (size_t)(n0 + ty + r) * K + k0 + tx;
        __nv_bfloat16 h = __float2bfloat16(v);
        hi[o] = h;
        lo[o] = __float2bfloat16(v - __bfloat162float(h));
    }
}

// ---------------------------------------------------------------------------
// Attention: one CTA per (window, head); outputs bf16 hi/lo.
// ---------------------------------------------------------------------------
#define KT_STRIDE 50

__global__ void __launch_bounds__(128)
attn_kernel(const float* __restrict__ qkv,
            const float* __restrict__ mask,
            const float* __restrict__ bias_table,
            __nv_bfloat16* __restrict__ out_hi,
            __nv_bfloat16* __restrict__ out_lo)
{
    const int bh = blockIdx.x;
    const int b  = bh / NHEADS;
    const int h  = bh - b * NHEADS;
    const int w  = b & (NW - 1);

    __shared__ float qs[NTOK * HDIM];
    __shared__ float kt[HDIM * KT_STRIDE];
    __shared__ float vs[NTOK * HDIM];
    __shared__ float pbuf[4][64];

    const int tid = threadIdx.x;
    const float* base = qkv + (size_t)b * NTOK * QKV_N + h * HDIM;

    for (int idx = tid; idx < NTOK * HDIM; idx += 128) {
        int i = idx >> 5, d = idx & 31;
        size_t roff = (size_t)i * QKV_N + d;
        qs[idx]               = base[roff];
        kt[d * KT_STRIDE + i] = base[roff + DMODEL];
        vs[idx]               = base[roff + 2 * DMODEL];
    }
    __syncthreads();

    const int warp = tid >> 5, lane = tid & 31;
    const float scale = 0.17677669529663687f;
    const float* mrow_base = mask + (size_t)w * NTOK * NTOK;

    for (int i = warp; i < NTOK; i += 4) {
        const int yi = i / 7, xi = i - yi * 7;
        const float* mrow = mrow_base + i * NTOK;

        float l1, l2 = -1e30f;
        {
            int j = lane;
            float a = 0.f;
#pragma unroll
            for (int d = 0; d < HDIM; d++)
                a += qs[i * HDIM + d] * kt[d * KT_STRIDE + j];
            int yj = j / 7, xj = j - yj * 7;
            int ridx = (yi - yj + 6) * 13 + (xi - xj + 6);
            l1 = a * scale + bias_table[ridx * NHEADS + h] + mrow[j];
        }
        if (lane < NTOK - 32) {
            int j = lane + 32;
            float a = 0.f;
#pragma unroll
            for (int d = 0; d < HDIM; d++)
                a += qs[i * HDIM + d] * kt[d * KT_STRIDE + j];
            int yj = j / 7, xj = j - yj * 7;
            int ridx = (yi - yj + 6) * 13 + (xi - xj + 6);
            l2 = a * scale + bias_table[ridx * NHEADS + h] + mrow[j];
        }

        float m = fmaxf(l1, l2);
#pragma unroll
        for (int o = 16; o > 0; o >>= 1)
            m = fmaxf(m, __shfl_xor_sync(0xffffffffu, m, o));
        float p1 = __expf(l1 - m);
        float p2 = (lane < NTOK - 32) ? __expf(l2 - m) : 0.f;
        float s = p1 + p2;
#pragma unroll
        for (int o = 16; o > 0; o >>= 1)
            s += __shfl_xor_sync(0xffffffffu, s, o);
        float inv = 1.f / s;

        pbuf[warp][lane] = p1 * inv;
        if (lane < NTOK - 32) pbuf[warp][lane + 32] = p2 * inv;
        __syncwarp();

        float a = 0.f;
#pragma unroll
        for (int j = 0; j < NTOK; j++)
            a += pbuf[warp][j] * vs[j * HDIM + lane];

        size_t oidx = ((size_t)b * NTOK + i) * DMODEL + h * HDIM + lane;
        __nv_bfloat16 hh = __float2bfloat16(a);
        out_hi[oidx] = hh;
        out_lo[oidx] = __float2bfloat16(a - __bfloat162float(hh));
        __syncwarp();
    }
}

// ---------------------------------------------------------------------------
// launch
// ---------------------------------------------------------------------------
extern "C" void kernel_launch(void* const* d_in, const int* in_sizes, int n_in,
                              void* d_out, int out_size)
{
    const float* x          = (const float*)d_in[0];
    const float* mask       = (const float*)d_in[1];
    const float* qkv_w      = (const float*)d_in[2];
    const float* qkv_b      = (const float*)d_in[3];
    const float* proj_w     = (const float*)d_in[4];
    const float* proj_b     = (const float*)d_in[5];
    const float* bias_table = (const float*)d_in[6];
    float* out = (float*)d_out;

    float *qkv_s;
    __nv_bfloat16 *xhi, *xlo, *ahi, *alo, *w1hi, *w1lo, *w2hi, *w2lo;
    cudaGetSymbolAddress((void**)&qkv_s, g_qkv);
    cudaGetSymbolAddress((void**)&xhi,  g_xhi);
    cudaGetSymbolAddress((void**)&xlo,  g_xlo);
    cudaGetSymbolAddress((void**)&ahi,  g_ahi);
    cudaGetSymbolAddress((void**)&alo,  g_alo);
    cudaGetSymbolAddress((void**)&w1hi, g_w1hi);
    cudaGetSymbolAddress((void**)&w1lo, g_w1lo);
    cudaGetSymbolAddress((void**)&w2hi, g_w2hi);
    cudaGetSymbolAddress((void**)&w2lo, g_w2lo);

    cudaFuncSetAttribute(gemm_mma_kernel,
                         cudaFuncAttributeMaxDynamicSharedMemorySize, SMEM_TOTAL);

    // 0) conversions
    {
        int n4 = (MROWS * KDIM) / 4;
        split_kernel<<<(n4 + 255) / 256, 256>>>((const float4*)x,
                                                (uint2*)xhi, (uint2*)xlo, n4);
        dim3 g1(QKV_N / 32, KDIM / 32);
        wtrans_split_kernel<<<g1, 256>>>(qkv_w, w1hi, w1lo, KDIM, QKV_N);
        dim3 g2(DMODEL / 32, KDIM / 32);
        wtrans_split_kernel<<<g2, 256>>>(proj_w, w2hi, w2lo, KDIM, DMODEL);
    }
    // 1) QKV GEMM
    {
        dim3 grid(QKV_N / BN, MROWS / BM);
        gemm_mma_kernel<<<grid, 256, SMEM_TOTAL>>>(xhi, xlo, w1hi, w1lo,
                                                   qkv_b, qkv_s, QKV_N);
    }
    // 2) attention
    attn_kernel<<<B_WIN * NHEADS, 128>>>(qkv_s, mask, bias_table, ahi, alo);

    // 3) proj GEMM -> d_out
    {
        dim3 grid(DMODEL / BN, MROWS / BM);
        gemm_mma_kernel<<<grid, 256, SMEM_TOTAL>>>(ahi, alo, w2hi, w2lo,
                                                   proj_b, out, DMODEL);
    }
}

// round 4
// speedup vs baseline: 2.0205x; 1.0225x over previous
#include <cuda_runtime.h>
#include <cuda_bf16.h>
#include <cstdint>

// ---------------------------------------------------------------------------
// Problem constants
// ---------------------------------------------------------------------------
#define B_WIN   2048
#define NTOK    49
#define DMODEL  768
#define NHEADS  24
#define HDIM    32
#define NW      64
#define MROWS   (B_WIN * NTOK)     // 100352
#define QKV_N   (3 * DMODEL)       // 2304
#define KDIM    768
#define KPITCH  (KDIM * 2)         // bytes per K-major row (bf16)

// ---------------------------------------------------------------------------
// scratch (__device__ globals, allocation-free)
// ---------------------------------------------------------------------------
__device__ float         g_qkv [(size_t)MROWS * QKV_N];
__device__ __nv_bfloat16 g_xhi [(size_t)MROWS * KDIM];
__device__ __nv_bfloat16 g_xlo [(size_t)MROWS * KDIM];
__device__ __nv_bfloat16 g_ahi [(size_t)MROWS * KDIM];
__device__ __nv_bfloat16 g_alo [(size_t)MROWS * KDIM];
__device__ __nv_bfloat16 g_w1hi[(size_t)QKV_N * KDIM];
__device__ __nv_bfloat16 g_w1lo[(size_t)QKV_N * KDIM];
__device__ __nv_bfloat16 g_w2hi[(size_t)DMODEL * KDIM];
__device__ __nv_bfloat16 g_w2lo[(size_t)DMODEL * KDIM];

// ---------------------------------------------------------------------------
// PTX helpers
// ---------------------------------------------------------------------------
__device__ __forceinline__ void cp16(uint32_t dst, const void* src) {
    asm volatile("cp.async.cg.shared.global [%0], [%1], 16;"
                 :: "r"(dst), "l"((unsigned long long)__cvta_generic_to_global(src))
                 : "memory");
}
__device__ __forceinline__ void ldsm4(uint32_t* r, uint32_t addr) {
    asm volatile("ldmatrix.sync.aligned.m8n8.x4.shared.b16 {%0,%1,%2,%3}, [%4];"
                 : "=r"(r[0]), "=r"(r[1]), "=r"(r[2]), "=r"(r[3]) : "r"(addr));
}
__device__ __forceinline__ void mma_bf16(float* c, const uint32_t* a,
                                         uint32_t b0, uint32_t b1) {
    asm volatile(
        "mma.sync.aligned.m16n8k16.row.col.f32.bf16.bf16.f32 "
        "{%0,%1,%2,%3}, {%4,%5,%6,%7}, {%8,%9}, {%0,%1,%2,%3};"
        : "+f"(c[0]), "+f"(c[1]), "+f"(c[2]), "+f"(c[3])
        : "r"(a[0]), "r"(a[1]), "r"(a[2]), "r"(a[3]), "r"(b0), "r"(b1));
}

// ---------------------------------------------------------------------------
// GEMM: C[M,N] = (Ahi+Alo)[M,K] @ (Bhi+Blo)^T[N,K] + bias, fp32 out.
// 3-term split-bf16. BM=128, BN=256, BK=32, 3-stage cp.async, 256 threads.
// Term-major MMA emission: same-acc dependency distance = 8 MMAs.
// ---------------------------------------------------------------------------
#define BM 128
#define BN 256
#define BK 32
#define NCHUNK (KDIM / BK)      // 24
#define ROWB 80
#define AHI_OFF 0
#define ALO_OFF (128 * ROWB)
#define BHI_OFF (2 * 128 * ROWB)
#define BLO_OFF (BHI_OFF + 256 * ROWB)
#define STG_B   (BLO_OFF + 256 * ROWB)  // 61440
#define SMEM_TOTAL (3 * STG_B)          // 184320

extern __shared__ char dyn_smem[];

__global__ void __launch_bounds__(256, 1)
gemm_mma_kernel(const __nv_bfloat16* __restrict__ Ahi,
                const __nv_bfloat16* __restrict__ Alo,
                const __nv_bfloat16* __restrict__ Bhi,
                const __nv_bfloat16* __restrict__ Blo,
                const float* __restrict__ bias,
                float* __restrict__ C, int N)
{
    const uint32_t sb = (uint32_t)__cvta_generic_to_shared(dyn_smem);
    const int tid    = threadIdx.x;
    const int wid    = tid >> 5;
    const int lane   = tid & 31;
    const int warp_m = wid & 1;
    const int warp_n = wid >> 1;
    const int brow   = blockIdx.y * BM;
    const int bcol   = blockIdx.x * BN;

    const char* pAhi = (const char*)Ahi + (size_t)brow * KPITCH;
    const char* pAlo = (const char*)Alo + (size_t)brow * KPITCH;
    const char* pBhi = (const char*)Bhi + (size_t)bcol * KPITCH;
    const char* pBlo = (const char*)Blo + (size_t)bcol * KPITCH;

    float acc[4][8][4];
#pragma unroll
    for (int mt = 0; mt < 4; mt++)
#pragma unroll
        for (int nt = 0; nt < 8; nt++)
#pragma unroll
            for (int q = 0; q < 4; q++) acc[mt][nt][q] = 0.f;

    auto load_stage = [&](int c, int s) {
        const uint32_t st = sb + s * STG_B;
        const int koff = c * (BK * 2);
#pragma unroll
        for (int r = 0; r < 2; r++) {
            int p    = tid + r * 256;
            int row  = p >> 2;
            int colb = (p & 3) << 4;
            size_t   go = (size_t)row * KPITCH + koff + colb;
            uint32_t so = row * ROWB + colb;
            cp16(st + AHI_OFF + so, pAhi + go);
            cp16(st + ALO_OFF + so, pAlo + go);
        }
#pragma unroll
        for (int r = 0; r < 4; r++) {
            int p    = tid + r * 256;
            int row  = p >> 2;
            int colb = (p & 3) << 4;
            size_t   go = (size_t)row * KPITCH + koff + colb;
            uint32_t so = row * ROWB + colb;
            cp16(st + BHI_OFF + so, pBhi + go);
            cp16(st + BLO_OFF + so, pBlo + go);
        }
        asm volatile("cp.async.commit_group;" ::: "memory");
    };

    load_stage(0, 0);
    load_stage(1, 1);

    for (int c = 0; c < NCHUNK; c++) {
        if (c < NCHUNK - 1)
            asm volatile("cp.async.wait_group 1;" ::: "memory");
        else
            asm volatile("cp.async.wait_group 0;" ::: "memory");
        __syncthreads();

        if (c + 2 < NCHUNK) load_stage(c + 2, (c + 2) % 3);

        const uint32_t st = sb + (c % 3) * STG_B;
#pragma unroll
        for (int ks = 0; ks < 2; ks++) {
            const int kb = ks * 32;
            uint32_t ahi[4][4], alo[4][4];
#pragma unroll
            for (int mt = 0; mt < 4; mt++) {
                int row = warp_m * 64 + mt * 16 + (lane & 7) + ((lane >> 3) & 1) * 8;
                uint32_t addr = st + row * ROWB + kb + ((lane >> 4) & 1) * 16;
                ldsm4(ahi[mt], addr + AHI_OFF);
                ldsm4(alo[mt], addr + ALO_OFF);
            }
#pragma unroll
            for (int np = 0; np < 4; np++) {
                int rowb = warp_n * 64 + np * 16 + (lane & 7) + ((lane >> 4) & 1) * 8;
                uint32_t addr = st + rowb * ROWB + kb + ((lane >> 3) & 1) * 16;
                uint32_t bh[4], bl[4];
                ldsm4(bh, addr + BHI_OFF);
                ldsm4(bl, addr + BLO_OFF);
                // term-major: dependency distance 8 between same-acc MMAs
#pragma unroll
                for (int t = 0; t < 2; t++)
#pragma unroll
                    for (int mt = 0; mt < 4; mt++)
                        mma_bf16(acc[mt][np * 2 + t], ahi[mt], bh[t*2], bh[t*2+1]);
#pragma unroll
                for (int t = 0; t < 2; t++)
#pragma unroll
                    for (int mt = 0; mt < 4; mt++)
                        mma_bf16(acc[mt][np * 2 + t], ahi[mt], bl[t*2], bl[t*2+1]);
#pragma unroll
                for (int t = 0; t < 2; t++)
#pragma unroll
                    for (int mt = 0; mt < 4; mt++)
                        mma_bf16(acc[mt][np * 2 + t], alo[mt], bh[t*2], bh[t*2+1]);
            }
        }
    }

    const int row0 = brow + warp_m * 64;
    const int col0 = bcol + warp_n * 64;
#pragma unroll
    for (int mt = 0; mt < 4; mt++) {
#pragma unroll
        for (int nt = 0; nt < 8; nt++) {
            int r  = row0 + mt * 16 + (lane >> 2);
            int cc = col0 + nt * 8 + (lane & 3) * 2;
            float2 bv = *(const float2*)(bias + cc);
            float2 o0 = make_float2(acc[mt][nt][0] + bv.x, acc[mt][nt][1] + bv.y);
            float2 o1 = make_float2(acc[mt][nt][2] + bv.x, acc[mt][nt][3] + bv.y);
            *(float2*)(C + (size_t)r * N + cc)       = o0;
            *(float2*)(C + (size_t)(r + 8) * N + cc) = o1;
        }
    }
}

// ---------------------------------------------------------------------------
// split f32 -> (hi, lo) bf16
// ---------------------------------------------------------------------------
__global__ void __launch_bounds__(256)
split_kernel(const float4* __restrict__ in, uint2* __restrict__ hi,
             uint2* __restrict__ lo, int n4)
{
    int i = blockIdx.x * 256 + threadIdx.x;
    if (i >= n4) return;
    float4 v = in[i];
    __nv_bfloat16 h0 = __float2bfloat16(v.x);
    __nv_bfloat16 h1 = __float2bfloat16(v.y);
    __nv_bfloat16 h2 = __float2bfloat16(v.z);
    __nv_bfloat16 h3 = __float2bfloat16(v.w);
    __nv_bfloat16 l0 = __float2bfloat16(v.x - __bfloat162float(h0));
    __nv_bfloat16 l1 = __float2bfloat16(v.y - __bfloat162float(h1));
    __nv_bfloat16 l2 = __float2bfloat16(v.z - __bfloat162float(h2));
    __nv_bfloat16 l3 = __float2bfloat16(v.w - __bfloat162float(h3));
    __nv_bfloat162 hh0 = {h0, h1}, hh1 = {h2, h3};
    __nv_bfloat162 ll0 = {l0, l1}, ll1 = {l2, l3};
    uint2 ho, lw;
    ho.x = *(uint32_t*)&hh0; ho.y = *(uint32_t*)&hh1;
    lw.x = *(uint32_t*)&ll0; lw.y = *(uint32_t*)&ll1;
    hi[i] = ho; lo[i] = lw;
}

// ---------------------------------------------------------------------------
// weight transpose + split: W[K,N] f32 -> hi/lo[N,K] bf16
// ---------------------------------------------------------------------------
__global__ void __launch_bounds__(256)
wtrans_split_kernel(const float* __restrict__ W, __nv_bfloat16* __restrict__ hi,
                    __nv_bfloat16* __restrict__ lo, int K, int N)
{
    __shared__ float t[32][33];
    const int n0 = blockIdx.x * 32, k0 = blockIdx.y * 32;
    const int tx = threadIdx.x & 31, ty = threadIdx.x >> 5;
#pragma unroll
    for (int r = 0; r < 32; r += 8)
        t[ty + r][tx] = W[(size_t)(k0 + ty + r) * N + n0 + tx];
    __syncthreads();
#pragma unroll
    for (int r = 0; r < 32; r += 8) {
        float v = t[tx][ty + r];
        size_t o = (size_t)(n0 + ty + r) * K + k0 + tx;
        __nv_bfloat16 h = __float2bfloat16(v);
        hi[o] = h;
        lo[o] = __float2bfloat16(v - __bfloat162float(h));
    }
}

// ---------------------------------------------------------------------------
// Attention: one CTA per (window, head). K rows in registers; V transposed
// in smem for float4 p.v; q via float4 broadcasts. f32 math throughout.
// ---------------------------------------------------------------------------
#define KS_STRIDE 36   // floats per k row (144B, 16B aligned, conflict-free)
#define VT_STRIDE 52   // floats per vt row (208B, 16B aligned, conflict-free)

__global__ void __launch_bounds__(128)
attn_kernel(const float* __restrict__ qkv,
            const float* __restrict__ mask,
            const float* __restrict__ bias_table,
            __nv_bfloat16* __restrict__ out_hi,
            __nv_bfloat16* __restrict__ out_lo)
{
    const int bh = blockIdx.x;
    const int b  = bh / NHEADS;
    const int h  = bh - b * NHEADS;
    const int w  = b & (NW - 1);

    __shared__ float qs[NTOK * HDIM];              // q[i][d], stride 32
    __shared__ float ks[NTOK * KS_STRIDE];         // k[j][d]
    __shared__ float vt[HDIM * VT_STRIDE];         // v^T[d][j]
    __shared__ float pbuf[4][64];

    const int tid = threadIdx.x;
    const float* base = qkv + (size_t)b * NTOK * QKV_N + h * HDIM;

    for (int idx = tid; idx < NTOK * HDIM; idx += 128) {
        int i = idx >> 5, d = idx & 31;
        size_t roff = (size_t)i * QKV_N + d;
        qs[idx]                 = base[roff];
        ks[i * KS_STRIDE + d]   = base[roff + DMODEL];
        vt[d * VT_STRIDE + i]   = base[roff + 2 * DMODEL];
    }
    // zero-pad vt columns 49..51 (read by the float4 tail with p=0)
    if (tid < HDIM) {
        vt[tid * VT_STRIDE + 49] = 0.f;
        vt[tid * VT_STRIDE + 50] = 0.f;
        vt[tid * VT_STRIDE + 51] = 0.f;
    }
    __syncthreads();

    const int warp = tid >> 5, lane = tid & 31;
    const float scale = 0.17677669529663687f;
    const float* mrow_base = mask + (size_t)w * NTOK * NTOK;

    // K rows into registers: k1 = k[lane][:], k2 = k[lane+32][:] (lane<17)
    float k1[32], k2[32];
#pragma unroll
    for (int m = 0; m < 8; m++)
        *(float4*)&k1[4 * m] = *(const float4*)&ks[lane * KS_STRIDE + 4 * m];
    if (lane < NTOK - 32) {
#pragma unroll
        for (int m = 0; m < 8; m++)
            *(float4*)&k2[4 * m] =
                *(const float4*)&ks[(lane + 32) * KS_STRIDE + 4 * m];
    } else {
#pragma unroll
        for (int m = 0; m < 32; m++) k2[m] = 0.f;
    }

    const int yq = lane / 7,        xq = lane - yq * 7;          // j = lane
    const int j2 = lane + 32;
    const int yq2 = j2 / 7,         xq2 = j2 - yq2 * 7;          // j = lane+32

    for (int i = warp; i < NTOK; i += 4) {
        const int yi = i / 7, xi = i - yi * 7;
        const float* mrow = mrow_base + (size_t)i * NTOK;

        float d1 = 0.f, d2 = 0.f;
#pragma unroll
        for (int m = 0; m < 8; m++) {
            float4 qv = *(const float4*)&qs[i * HDIM + 4 * m];   // broadcast
            d1 += qv.x * k1[4*m] + qv.y * k1[4*m+1] + qv.z * k1[4*m+2] + qv.w * k1[4*m+3];
            d2 += qv.x * k2[4*m] + qv.y * k2[4*m+1] + qv.z * k2[4*m+2] + qv.w * k2[4*m+3];
        }
        float l1 = d1 * scale
                 + bias_table[((yi - yq + 6) * 13 + (xi - xq + 6)) * NHEADS + h]
                 + mrow[lane];
        float l2 = -1e30f;
        if (lane < NTOK - 32)
            l2 = d2 * scale
               + bias_table[((yi - yq2 + 6) * 13 + (xi - xq2 + 6)) * NHEADS + h]
               + mrow[j2];

        float m = fmaxf(l1, l2);
#pragma unroll
        for (int o = 16; o > 0; o >>= 1)
            m = fmaxf(m, __shfl_xor_sync(0xffffffffu, m, o));
        float p1 = __expf(l1 - m);
        float p2 = (lane < NTOK - 32) ? __expf(l2 - m) : 0.f;
        float s = p1 + p2;
#pragma unroll
        for (int o = 16; o > 0; o >>= 1)
            s += __shfl_xor_sync(0xffffffffu, s, o);
        float inv = 1.f / s;

        pbuf[warp][lane]      = p1 * inv;
        pbuf[warp][lane + 32] = p2 * inv;     // zero for lane>=17 incl. 49..63
        __syncwarp();

        float acc = 0.f;
#pragma unroll
        for (int j4 = 0; j4 < 13; j4++) {
            float4 pv = *(const float4*)&pbuf[warp][j4 * 4];         // broadcast
            float4 vv = *(const float4*)&vt[lane * VT_STRIDE + j4 * 4];
            acc += pv.x * vv.x + pv.y * vv.y + pv.z * vv.z + pv.w * vv.w;
        }

        size_t oidx = ((size_t)b * NTOK + i) * DMODEL + h * HDIM + lane;
        __nv_bfloat16 hh = __float2bfloat16(acc);
        out_hi[oidx] = hh;
        out_lo[oidx] = __float2bfloat16(acc - __bfloat162float(hh));
        __syncwarp();
    }
}

// ---------------------------------------------------------------------------
// launch
// ---------------------------------------------------------------------------
extern "C" void kernel_launch(void* const* d_in, const int* in_sizes, int n_in,
                              void* d_out, int out_size)
{
    const float* x          = (const float*)d_in[0];
    const float* mask       = (const float*)d_in[1];
    const float* qkv_w      = (const float*)d_in[2];
    const float* qkv_b      = (const float*)d_in[3];
    const float* proj_w     = (const float*)d_in[4];
    const float* proj_b     = (const float*)d_in[5];
    const float* bias_table = (const float*)d_in[6];
    float* out = (float*)d_out;

    float *qkv_s;
    __nv_bfloat16 *xhi, *xlo, *ahi, *alo, *w1hi, *w1lo, *w2hi, *w2lo;
    cudaGetSymbolAddress((void**)&qkv_s, g_qkv);
    cudaGetSymbolAddress((void**)&xhi,  g_xhi);
    cudaGetSymbolAddress((void**)&xlo,  g_xlo);
    cudaGetSymbolAddress((void**)&ahi,  g_ahi);
    cudaGetSymbolAddress((void**)&alo,  g_alo);
    cudaGetSymbolAddress((void**)&w1hi, g_w1hi);
    cudaGetSymbolAddress((void**)&w1lo, g_w1lo);
    cudaGetSymbolAddress((void**)&w2hi, g_w2hi);
    cudaGetSymbolAddress((void**)&w2lo, g_w2lo);

    cudaFuncSetAttribute(gemm_mma_kernel,
                         cudaFuncAttributeMaxDynamicSharedMemorySize, SMEM_TOTAL);

    {
        int n4 = (MROWS * KDIM) / 4;
        split_kernel<<<(n4 + 255) / 256, 256>>>((const float4*)x,
                                                (uint2*)xhi, (uint2*)xlo, n4);
        dim3 g1(QKV_N / 32, KDIM / 32);
        wtrans_split_kernel<<<g1, 256>>>(qkv_w, w1hi, w1lo, KDIM, QKV_N);
        dim3 g2(DMODEL / 32, KDIM / 32);
        wtrans_split_kernel<<<g2, 256>>>(proj_w, w2hi, w2lo, KDIM, DMODEL);
    }
    {
        dim3 grid(QKV_N / BN, MROWS / BM);
        gemm_mma_kernel<<<grid, 256, SMEM_TOTAL>>>(xhi, xlo, w1hi, w1lo,
                                                   qkv_b, qkv_s, QKV_N);
    }
    attn_kernel<<<B_WIN * NHEADS, 128>>>(qkv_s, mask, bias_table, ahi, alo);
    {
        dim3 grid(DMODEL / BN, MROWS / BM);
        gemm_mma_kernel<<<grid, 256, SMEM_TOTAL>>>(ahi, alo, w2hi, w2lo,
                                                   proj_b, out, DMODEL);
    }
}

// round 5
// speedup vs baseline: 2.4168x; 1.1961x over previous
#include <cuda_runtime.h>
#include <cuda_bf16.h>
#include <cstdint>

// ---------------------------------------------------------------------------
// Problem constants
// ---------------------------------------------------------------------------
#define B_WIN   2048
#define NTOK    49
#define DMODEL  768
#define NHEADS  24
#define HDIM    32
#define NW      64
#define MROWS   (B_WIN * NTOK)     // 100352
#define QKV_N   (3 * DMODEL)       // 2304
#define KDIM    768
#define KPITCH  (KDIM * 2)         // bytes per K-major row (bf16)

// ---------------------------------------------------------------------------
// scratch (__device__ globals, allocation-free)
// ---------------------------------------------------------------------------
__device__ float         g_qkv [(size_t)MROWS * QKV_N];
__device__ __nv_bfloat16 g_xhi [(size_t)MROWS * KDIM];
__device__ __nv_bfloat16 g_xlo [(size_t)MROWS * KDIM];
__device__ __nv_bfloat16 g_ahi [(size_t)MROWS * KDIM];
__device__ __nv_bfloat16 g_alo [(size_t)MROWS * KDIM];
__device__ __nv_bfloat16 g_w1hi[(size_t)QKV_N * KDIM];
__device__ __nv_bfloat16 g_w1lo[(size_t)QKV_N * KDIM];
__device__ __nv_bfloat16 g_w2hi[(size_t)DMODEL * KDIM];
__device__ __nv_bfloat16 g_w2lo[(size_t)DMODEL * KDIM];

// ---------------------------------------------------------------------------
// PTX helpers
// ---------------------------------------------------------------------------
__device__ __forceinline__ void cp16(uint32_t dst, const void* src) {
    asm volatile("cp.async.cg.shared.global [%0], [%1], 16;"
                 :: "r"(dst), "l"((unsigned long long)__cvta_generic_to_global(src))
                 : "memory");
}
__device__ __forceinline__ void ldsm4(uint32_t* r, uint32_t addr) {
    asm volatile("ldmatrix.sync.aligned.m8n8.x4.shared.b16 {%0,%1,%2,%3}, [%4];"
                 : "=r"(r[0]), "=r"(r[1]), "=r"(r[2]), "=r"(r[3]) : "r"(addr));
}
__device__ __forceinline__ void mma_bf16(float* c, const uint32_t* a,
                                         uint32_t b0, uint32_t b1) {
    asm volatile(
        "mma.sync.aligned.m16n8k16.row.col.f32.bf16.bf16.f32 "
        "{%0,%1,%2,%3}, {%4,%5,%6,%7}, {%8,%9}, {%0,%1,%2,%3};"
        : "+f"(c[0]), "+f"(c[1]), "+f"(c[2]), "+f"(c[3])
        : "r"(a[0]), "r"(a[1]), "r"(a[2]), "r"(a[3]), "r"(b0), "r"(b1));
}
// packed fp32x2 (Blackwell FFMA2 — PTX-only)
__device__ __forceinline__ unsigned long long dup_f32(float x) {
    unsigned long long r;
    asm("mov.b64 %0, {%1, %1};" : "=l"(r) : "f"(x));
    return r;
}
__device__ __forceinline__ unsigned long long pack_f32(float lo, float hi) {
    unsigned long long r;
    asm("mov.b64 %0, {%1, %2};" : "=l"(r) : "f"(lo), "f"(hi));
    return r;
}
__device__ __forceinline__ void fma2(unsigned long long& d,
                                     unsigned long long a,
                                     unsigned long long b) {
    asm("fma.rn.f32x2 %0, %1, %2, %0;" : "+l"(d) : "l"(a), "l"(b));
}
__device__ __forceinline__ void unpack2(unsigned long long v, float& lo, float& hi) {
    asm("mov.b64 {%0, %1}, %2;" : "=f"(lo), "=f"(hi) : "l"(v));
}

// ---------------------------------------------------------------------------
// GEMM: C[M,N] = (Ahi+Alo)[M,K] @ (Bhi+Blo)^T[N,K] + bias, fp32 out.
// 3-term split-bf16. BM=128, BN=128, BK=32, 3-stage cp.async, 256 threads.
// 64B smem rows with XOR swizzle (no pad) -> 96KB total -> 2 CTAs/SM.
// swizzled 16B-slot: c16' = c16 ^ ((row>>1)&3)
// ---------------------------------------------------------------------------
#define BM 128
#define BN 128
#define BK 32
#define NCHUNK (KDIM / BK)      // 24
#define AHI_OFF 0
#define ALO_OFF 8192
#define BHI_OFF 16384
#define BLO_OFF 24576
#define STG_B   32768
#define SMEM_TOTAL (3 * STG_B)  // 98304

extern __shared__ char dyn_smem[];

__device__ __forceinline__ uint32_t swz_off(int row, int c16) {
    return (uint32_t)(row * 64 + (((c16) ^ ((row >> 1) & 3)) << 4));
}

__global__ void __launch_bounds__(256, 2)
gemm_mma_kernel(const __nv_bfloat16* __restrict__ Ahi,
                const __nv_bfloat16* __restrict__ Alo,
                const __nv_bfloat16* __restrict__ Bhi,
                const __nv_bfloat16* __restrict__ Blo,
                const float* __restrict__ bias,
                float* __restrict__ C, int N)
{
    const uint32_t sb = (uint32_t)__cvta_generic_to_shared(dyn_smem);
    const int tid    = threadIdx.x;
    const int wid    = tid >> 5;
    const int lane   = tid & 31;
    const int warp_m = wid & 1;     // 0..1 -> 64 rows
    const int warp_n = wid >> 1;    // 0..3 -> 32 cols
    const int brow   = blockIdx.y * BM;
    const int bcol   = blockIdx.x * BN;

    const char* pAhi = (const char*)Ahi + (size_t)brow * KPITCH;
    const char* pAlo = (const char*)Alo + (size_t)brow * KPITCH;
    const char* pBhi = (const char*)Bhi + (size_t)bcol * KPITCH;
    const char* pBlo = (const char*)Blo + (size_t)bcol * KPITCH;

    float acc[4][4][4];
#pragma unroll
    for (int mt = 0; mt < 4; mt++)
#pragma unroll
        for (int nt = 0; nt < 4; nt++)
#pragma unroll
            for (int q = 0; q < 4; q++) acc[mt][nt][q] = 0.f;

    auto load_stage = [&](int c, int s) {
        const uint32_t st = sb + s * STG_B;
        const int koff = c * 64;   // bytes within K row
#pragma unroll
        for (int r = 0; r < 2; r++) {
            int p    = tid + r * 256;      // 0..511
            int row  = p >> 2;             // 0..127
            int c16  = p & 3;
            uint32_t so = swz_off(row, c16);
            size_t   go = (size_t)row * KPITCH + koff + c16 * 16;
            cp16(st + AHI_OFF + so, pAhi + go);
            cp16(st + ALO_OFF + so, pAlo + go);
            cp16(st + BHI_OFF + so, pBhi + go);
            cp16(st + BLO_OFF + so, pBlo + go);
        }
        asm volatile("cp.async.commit_group;" ::: "memory");
    };

    load_stage(0, 0);
    load_stage(1, 1);

    for (int c = 0; c < NCHUNK; c++) {
        if (c < NCHUNK - 1)
            asm volatile("cp.async.wait_group 1;" ::: "memory");
        else
            asm volatile("cp.async.wait_group 0;" ::: "memory");
        __syncthreads();

        if (c + 2 < NCHUNK) load_stage(c + 2, (c + 2) % 3);

        const uint32_t st = sb + (c % 3) * STG_B;
#pragma unroll
        for (int ks = 0; ks < 2; ks++) {
            uint32_t ahi[4][4], alo[4][4];
#pragma unroll
            for (int mt = 0; mt < 4; mt++) {
                int row = warp_m * 64 + mt * 16 + (lane & 7) + ((lane >> 3) & 1) * 8;
                int c16 = 2 * ks + ((lane >> 4) & 1);
                uint32_t so = swz_off(row, c16);
                ldsm4(ahi[mt], st + AHI_OFF + so);
                ldsm4(alo[mt], st + ALO_OFF + so);
            }
            uint32_t bh[2][4], bl[2][4];
#pragma unroll
            for (int np = 0; np < 2; np++) {
                int rowb = warp_n * 32 + np * 16 + (lane & 7) + ((lane >> 4) & 1) * 8;
                int c16  = 2 * ks + ((lane >> 3) & 1);
                uint32_t so = swz_off(rowb, c16);
                ldsm4(bh[np], st + BHI_OFF + so);
                ldsm4(bl[np], st + BLO_OFF + so);
            }
            // term-major emission
#pragma unroll
            for (int np = 0; np < 2; np++)
#pragma unroll
                for (int t = 0; t < 2; t++)
#pragma unroll
                    for (int mt = 0; mt < 4; mt++)
                        mma_bf16(acc[mt][np*2+t], ahi[mt], bh[np][t*2], bh[np][t*2+1]);
#pragma unroll
            for (int np = 0; np < 2; np++)
#pragma unroll
                for (int t = 0; t < 2; t++)
#pragma unroll
                    for (int mt = 0; mt < 4; mt++)
                        mma_bf16(acc[mt][np*2+t], ahi[mt], bl[np][t*2], bl[np][t*2+1]);
#pragma unroll
            for (int np = 0; np < 2; np++)
#pragma unroll
                for (int t = 0; t < 2; t++)
#pragma unroll
                    for (int mt = 0; mt < 4; mt++)
                        mma_bf16(acc[mt][np*2+t], alo[mt], bh[np][t*2], bh[np][t*2+1]);
        }
    }

    const int row0 = brow + warp_m * 64;
    const int col0 = bcol + warp_n * 32;
#pragma unroll
    for (int mt = 0; mt < 4; mt++) {
#pragma unroll
        for (int nt = 0; nt < 4; nt++) {
            int r  = row0 + mt * 16 + (lane >> 2);
            int cc = col0 + nt * 8 + (lane & 3) * 2;
            float2 bv = *(const float2*)(bias + cc);
            float2 o0 = make_float2(acc[mt][nt][0] + bv.x, acc[mt][nt][1] + bv.y);
            float2 o1 = make_float2(acc[mt][nt][2] + bv.x, acc[mt][nt][3] + bv.y);
            *(float2*)(C + (size_t)r * N + cc)       = o0;
            *(float2*)(C + (size_t)(r + 8) * N + cc) = o1;
        }
    }
}

// ---------------------------------------------------------------------------
// split f32 -> (hi, lo) bf16
// ---------------------------------------------------------------------------
__global__ void __launch_bounds__(256)
split_kernel(const float4* __restrict__ in, uint2* __restrict__ hi,
             uint2* __restrict__ lo, int n4)
{
    int i = blockIdx.x * 256 + threadIdx.x;
    if (i >= n4) return;
    float4 v = in[i];
    __nv_bfloat16 h0 = __float2bfloat16(v.x);
    __nv_bfloat16 h1 = __float2bfloat16(v.y);
    __nv_bfloat16 h2 = __float2bfloat16(v.z);
    __nv_bfloat16 h3 = __float2bfloat16(v.w);
    __nv_bfloat16 l0 = __float2bfloat16(v.x - __bfloat162float(h0));
    __nv_bfloat16 l1 = __float2bfloat16(v.y - __bfloat162float(h1));
    __nv_bfloat16 l2 = __float2bfloat16(v.z - __bfloat162float(h2));
    __nv_bfloat16 l3 = __float2bfloat16(v.w - __bfloat162float(h3));
    __nv_bfloat162 hh0 = {h0, h1}, hh1 = {h2, h3};
    __nv_bfloat162 ll0 = {l0, l1}, ll1 = {l2, l3};
    uint2 ho, lw;
    ho.x = *(uint32_t*)&hh0; ho.y = *(uint32_t*)&hh1;
    lw.x = *(uint32_t*)&ll0; lw.y = *(uint32_t*)&ll1;
    hi[i] = ho; lo[i] = lw;
}

// ---------------------------------------------------------------------------
// weight transpose + split: W[K,N] f32 -> hi/lo[N,K] bf16
// ---------------------------------------------------------------------------
__global__ void __launch_bounds__(256)
wtrans_split_kernel(const float* __restrict__ W, __nv_bfloat16* __restrict__ hi,
                    __nv_bfloat16* __restrict__ lo, int K, int N)
{
    __shared__ float t[32][33];
    const int n0 = blockIdx.x * 32, k0 = blockIdx.y * 32;
    const int tx = threadIdx.x & 31, ty = threadIdx.x >> 5;
#pragma unroll
    for (int r = 0; r < 32; r += 8)
        t[ty + r][tx] = W[(size_t)(k0 + ty + r) * N + n0 + tx];
    __syncthreads();
#pragma unroll
    for (int r = 0; r < 32; r += 8) {
        float v = t[tx][ty + r];
        size_t o = (size_t)(n0 + ty + r) * K + k0 + tx;
        __nv_bfloat16 h = __float2bfloat16(v);
        hi[o] = h;
        lo[o] = __float2bfloat16(v - __bfloat162float(h));
    }
}

// ---------------------------------------------------------------------------
// Attention: one CTA per (window, head). K rows in packed f32x2 registers;
// q via float4 smem broadcasts; p.v with packed f32x2 over j-pairs.
// ---------------------------------------------------------------------------
#define KS_STRIDE 36
#define VT_STRIDE 52

__global__ void __launch_bounds__(128)
attn_kernel(const float* __restrict__ qkv,
            const float* __restrict__ mask,
            const float* __restrict__ bias_table,
            __nv_bfloat16* __restrict__ out_hi,
            __nv_bfloat16* __restrict__ out_lo)
{
    const int bh = blockIdx.x;
    const int b  = bh / NHEADS;
    const int h  = bh - b * NHEADS;
    const int w  = b & (NW - 1);

    __shared__ float qs[NTOK * HDIM];
    __shared__ float ks[NTOK * KS_STRIDE];
    __shared__ float vt[HDIM * VT_STRIDE];
    __shared__ float pbuf[4][64];
    __shared__ float bt[169];

    const int tid = threadIdx.x;
    const float* base = qkv + (size_t)b * NTOK * QKV_N + h * HDIM;

    for (int idx = tid; idx < NTOK * HDIM; idx += 128) {
        int i = idx >> 5, d = idx & 31;
        size_t roff = (size_t)i * QKV_N + d;
        qs[idx]               = base[roff];
        ks[i * KS_STRIDE + d] = base[roff + DMODEL];
        vt[d * VT_STRIDE + i] = base[roff + 2 * DMODEL];
    }
    if (tid < HDIM) {
        vt[tid * VT_STRIDE + 49] = 0.f;
        vt[tid * VT_STRIDE + 50] = 0.f;
        vt[tid * VT_STRIDE + 51] = 0.f;
    }
    for (int idx = tid; idx < 169; idx += 128)
        bt[idx] = bias_table[idx * NHEADS + h];
    __syncthreads();

    const int warp = tid >> 5, lane = tid & 31;
    const float scale = 0.17677669529663687f;
    const float* mrow_base = mask + (size_t)w * NTOK * NTOK;

    // K rows -> packed registers: kp[d] = {k[lane][d], k[lane+32][d]}
    unsigned long long kp[32];
    {
        float k1[32], k2[32];
#pragma unroll
        for (int m = 0; m < 8; m++)
            *(float4*)&k1[4 * m] = *(const float4*)&ks[lane * KS_STRIDE + 4 * m];
        if (lane < NTOK - 32) {
#pragma unroll
            for (int m = 0; m < 8; m++)
                *(float4*)&k2[4 * m] =
                    *(const float4*)&ks[(lane + 32) * KS_STRIDE + 4 * m];
        } else {
#pragma unroll
            for (int m = 0; m < 32; m++) k2[m] = 0.f;
        }
#pragma unroll
        for (int m = 0; m < 32; m++) kp[m] = pack_f32(k1[m], k2[m]);
    }

    const int yq  = lane / 7, xq  = lane - yq * 7;
    const int j2  = lane + 32;
    const int yq2 = j2 / 7,   xq2 = j2 - yq2 * 7;

    for (int i = warp; i < NTOK; i += 4) {
        const int yi = i / 7, xi = i - yi * 7;
        const float* mrow = mrow_base + (size_t)i * NTOK;

        unsigned long long d12 = 0ull;
#pragma unroll
        for (int m = 0; m < 8; m++) {
            float4 qv = *(const float4*)&qs[i * HDIM + 4 * m];  // broadcast
            fma2(d12, kp[4*m+0], dup_f32(qv.x));
            fma2(d12, kp[4*m+1], dup_f32(qv.y));
            fma2(d12, kp[4*m+2], dup_f32(qv.z));
            fma2(d12, kp[4*m+3], dup_f32(qv.w));
        }
        float d1, d2;
        unpack2(d12, d1, d2);

        float l1 = d1 * scale + bt[(yi - yq + 6) * 13 + (xi - xq + 6)] + mrow[lane];
        float l2 = -1e30f;
        if (lane < NTOK - 32)
            l2 = d2 * scale + bt[(yi - yq2 + 6) * 13 + (xi - xq2 + 6)] + mrow[j2];

        float m = fmaxf(l1, l2);
#pragma unroll
        for (int o = 16; o > 0; o >>= 1)
            m = fmaxf(m, __shfl_xor_sync(0xffffffffu, m, o));
        float p1 = __expf(l1 - m);
        float p2 = (lane < NTOK - 32) ? __expf(l2 - m) : 0.f;
        float s = p1 + p2;
#pragma unroll
        for (int o = 16; o > 0; o >>= 1)
            s += __shfl_xor_sync(0xffffffffu, s, o);
        float inv = 1.f / s;

        pbuf[warp][lane]      = p1 * inv;
        pbuf[warp][lane + 32] = p2 * inv;   // zero for lane>=17 (covers 49..63)
        __syncwarp();

        unsigned long long a2 = 0ull;
#pragma unroll
        for (int j4 = 0; j4 < 13; j4++) {
            ulonglong2 pq = *(const ulonglong2*)&pbuf[warp][j4 * 4];      // bcast
            ulonglong2 vq = *(const ulonglong2*)&vt[lane * VT_STRIDE + j4 * 4];
            fma2(a2, pq.x, vq.x);
            fma2(a2, pq.y, vq.y);
        }
        float alo_, ahi_;
        unpack2(a2, alo_, ahi_);
        float acc = alo_ + ahi_;

        size_t oidx = ((size_t)b * NTOK + i) * DMODEL + h * HDIM + lane;
        __nv_bfloat16 hh = __float2bfloat16(acc);
        out_hi[oidx] = hh;
        out_lo[oidx] = __float2bfloat16(acc - __bfloat162float(hh));
        __syncwarp();
    }
}

// ---------------------------------------------------------------------------
// launch
// ---------------------------------------------------------------------------
extern "C" void kernel_launch(void* const* d_in, const int* in_sizes, int n_in,
                              void* d_out, int out_size)
{
    const float* x          = (const float*)d_in[0];
    const float* mask       = (const float*)d_in[1];
    const float* qkv_w      = (const float*)d_in[2];
    const float* qkv_b      = (const float*)d_in[3];
    const float* proj_w     = (const float*)d_in[4];
    const float* proj_b     = (const float*)d_in[5];
    const float* bias_table = (const float*)d_in[6];
    float* out = (float*)d_out;

    float *qkv_s;
    __nv_bfloat16 *xhi, *xlo, *ahi, *alo, *w1hi, *w1lo, *w2hi, *w2lo;
    cudaGetSymbolAddress((void**)&qkv_s, g_qkv);
    cudaGetSymbolAddress((void**)&xhi,  g_xhi);
    cudaGetSymbolAddress((void**)&xlo,  g_xlo);
    cudaGetSymbolAddress((void**)&ahi,  g_ahi);
    cudaGetSymbolAddress((void**)&alo,  g_alo);
    cudaGetSymbolAddress((void**)&w1hi, g_w1hi);
    cudaGetSymbolAddress((void**)&w1lo, g_w1lo);
    cudaGetSymbolAddress((void**)&w2hi, g_w2hi);
    cudaGetSymbolAddress((void**)&w2lo, g_w2lo);

    cudaFuncSetAttribute(gemm_mma_kernel,
                         cudaFuncAttributeMaxDynamicSharedMemorySize, SMEM_TOTAL);

    {
        int n4 = (MROWS * KDIM) / 4;
        split_kernel<<<(n4 + 255) / 256, 256>>>((const float4*)x,
                                                (uint2*)xhi, (uint2*)xlo, n4);
        dim3 g1(QKV_N / 32, KDIM / 32);
        wtrans_split_kernel<<<g1, 256>>>(qkv_w, w1hi, w1lo, KDIM, QKV_N);
        dim3 g2(DMODEL / 32, KDIM / 32);
        wtrans_split_kernel<<<g2, 256>>>(proj_w, w2hi, w2lo, KDIM, DMODEL);
    }
    {
        dim3 grid(QKV_N / BN, MROWS / BM);
        gemm_mma_kernel<<<grid, 256, SMEM_TOTAL>>>(xhi, xlo, w1hi, w1lo,
                                                   qkv_b, qkv_s, QKV_N);
    }
    attn_kernel<<<B_WIN * NHEADS, 128>>>(qkv_s, mask, bias_table, ahi, alo);
    {
        dim3 grid(DMODEL / BN, MROWS / BM);
        gemm_mma_kernel<<<grid, 256, SMEM_TOTAL>>>(ahi, alo, w2hi, w2lo,
                                                   proj_b, out, DMODEL);
    }
}